// round 13
// baseline (speedup 1.0000x reference)
#include <cuda_runtime.h>
#include <cuda_fp16.h>
#include <cstdint>

#define BB 4
#define NN 16384
#define MM 16384
#define HH 32
#define KK 15
#define FF 64
#define CC 64
#define KF 960
#define TOTALP (BB * MM)      // 65536

// ---------------- Phase-A (HMMA) config ----------------
#define THREADS_A 256         // 8 warps, 1 point per warp
#define WARPS_A 8
#define FEATW 72              // halfs per feat row (144B)
#define WROW  40              // halfs per wT row (80B)
#define WARP_HALFS (HH * FEATW + 16 * WROW)   // 2944
#define SMEM_A (WARPS_A * WARP_HALFS * 2)     // 47104 B

// ---------------- GEMM config ----------------
#define PTS_CTA 256
#define THREADS_G 256
#define KCH 64
#define NCH (KF / KCH)        // 15
#define ROWB 144

#define ST_WF   0
#define ST_KV   (PTS_CTA * ROWB)            // 36864
#define ST_SIZE (ST_KV + CC * ROWB)         // 46080
#define SMEM_G  (2 * ST_SIZE)               // 92160

// ------------- device scratch -------------
// WF stored k-chunk-major: [k][p][64] halfs -> gemm chunk reads are contiguous
__device__ __half g_WF[(size_t)NCH * TOTALP * KCH];   // 120 MB fp16
__device__ __half g_feat16[(size_t)BB * NN * FF];     // 8.4 MB
__device__ __half g_KVT[CC * KF];                     // [c][kf]

// ------------- helpers -------------
__device__ __forceinline__ uint32_t smem_u32(const void* p) {
    uint32_t a;
    asm("{ .reg .u64 t; cvta.to.shared.u64 t, %1; cvt.u32.u64 %0, t; }" : "=r"(a) : "l"(p));
    return a;
}
__device__ __forceinline__ void cpasync16(uint32_t dst, const void* src) {
    asm volatile("cp.async.cg.shared.global [%0], [%1], 16;" :: "r"(dst), "l"(src));
}
__device__ __forceinline__ void cpasync_commit() { asm volatile("cp.async.commit_group;"); }
__device__ __forceinline__ uint32_t lds32(uint32_t a) {
    uint32_t v; asm volatile("ld.shared.b32 %0, [%1];" : "=r"(v) : "r"(a)); return v;
}
__device__ __forceinline__ void sts32(uint32_t a, uint32_t v) {
    asm volatile("st.shared.b32 [%0], %1;" :: "r"(a), "r"(v));
}
__device__ __forceinline__ void mma16816h(float* c, const uint32_t* a, const uint32_t* b) {
    asm volatile(
        "mma.sync.aligned.m16n8k16.row.col.f32.f16.f16.f32 "
        "{%0,%1,%2,%3}, {%4,%5,%6,%7}, {%8,%9}, {%0,%1,%2,%3};"
        : "+f"(c[0]), "+f"(c[1]), "+f"(c[2]), "+f"(c[3])
        : "r"(a[0]), "r"(a[1]), "r"(a[2]), "r"(a[3]), "r"(b[0]), "r"(b[1]));
}
__device__ __forceinline__ void ldmatrix_x4_t(uint32_t& r0, uint32_t& r1,
                                              uint32_t& r2, uint32_t& r3, uint32_t a) {
    asm volatile("ldmatrix.sync.aligned.m8n8.x4.trans.shared.b16 {%0,%1,%2,%3}, [%4];"
                 : "=r"(r0), "=r"(r1), "=r"(r2), "=r"(r3) : "r"(a));
}

// =================================================================
// Kernel 0: features fp32 -> fp16; first 240 blocks also prep KVT
// =================================================================
__global__ void prep_kernel(const float* __restrict__ features,
                            const float* __restrict__ k_values) {
    const int i = blockIdx.x * blockDim.x + threadIdx.x;
    if (blockIdx.x < 240) {
        const int j = blockIdx.x * 256 + threadIdx.x;   // 61440 = KF*CC
        const int kf = j >> 6, c = j & 63;
        g_KVT[c * KF + kf] = __float2half_rn(k_values[j]);
    }
    const float4 v = ((const float4*)features)[i];
    ((__half2*)g_feat16)[2 * i]     = __floats2half2_rn(v.x, v.y);
    ((__half2*)g_feat16)[2 * i + 1] = __floats2half2_rn(v.z, v.w);
}

// =================================================================
// Kernel 1: Phase A (HMMA) -> WF fp16 (k-major), staged coalesced epilogue
// =================================================================
__global__ void __launch_bounds__(THREADS_A, 3)
phaseA_kernel(const float* __restrict__ points,
              const float* __restrict__ output_points,
              const float* __restrict__ k_points,
              const int*   __restrict__ neighbor_indices)
{
    extern __shared__ __half smA[];
    __shared__ float kps[KK * 3 + 3];

    const int tid  = threadIdx.x;
    const int warp = tid >> 5;
    const int lane = tid & 31;
    const int g    = lane >> 2;
    const int t    = lane & 3;

    if (tid < KK * 3) kps[tid] = k_points[tid];
    __syncthreads();

    __half* featsm = smA + warp * WARP_HALFS;   // [32][FEATW]
    __half* wsmT   = featsm + HH * FEATW;       // [16][WROW]
    const uint32_t featb = smem_u32(featsm);
    const uint32_t wb    = smem_u32(wsmT);

    const int gp = blockIdx.x * WARPS_A + warp;
    const int b  = gp >> 14;

    // ---- load neighbor idx, immediately issue gather cp.asyncs ----
    const int nidx = neighbor_indices[gp * HH + lane];
    const __half* f16base = g_feat16 + (size_t)b * NN * FF;
    const int s = lane & 7;
    #pragma unroll
    for (int it = 0; it < 8; it++) {
        const int row = it * 4 + (lane >> 3);
        const int ni  = __shfl_sync(0xffffffffu, nidx, row);
        cpasync16(featb + row * (FEATW * 2) + s * 16,
                  f16base + (size_t)ni * FF + s * 8);
    }
    cpasync_commit();

    // ---- w compute (overlaps gather latency): lane = h ----
    wsmT[15 * WROW + lane] = __ushort_as_half(0);
    const float ox = output_points[gp * 3 + 0];
    const float oy = output_points[gp * 3 + 1];
    const float oz = output_points[gp * 3 + 2];
    const float* pp = points + ((size_t)b * NN + nidx) * 3;
    const float rx = pp[0] - ox;
    const float ry = pp[1] - oy;
    const float rz = pp[2] - oz;

    #pragma unroll
    for (int k = 0; k < KK; k++) {
        const float dx = rx - kps[k * 3 + 0];
        const float dy = ry - kps[k * 3 + 1];
        const float dz = rz - kps[k * 3 + 2];
        const float d  = sqrtf(fmaf(dx, dx, fmaf(dy, dy, dz * dz)));
        wsmT[k * WROW + lane] = __float2half_rn(fmaxf(1.0f - d, 0.0f));
    }

    asm volatile("cp.async.wait_group 0;" ::: "memory");
    __syncwarp();

    // ---- MMA: D[k16][f64] ----
    float acc[8][4];
    #pragma unroll
    for (int nt = 0; nt < 8; nt++)
        #pragma unroll
        for (int q = 0; q < 4; q++) acc[nt][q] = 0.0f;

    const int lm_h = ((lane >> 3) & 1) * 8 + (lane & 7);
    const int lm_f = ((lane >> 4) & 1) * 8;

    #pragma unroll
    for (int kstep = 0; kstep < 2; kstep++) {
        const int h0 = kstep * 16;
        uint32_t a[4];
        const uint32_t ab = wb + g * (WROW * 2) + kstep * 32 + t * 4;
        a[0] = lds32(ab);
        a[1] = lds32(ab + 8 * (WROW * 2));
        a[2] = lds32(ab + 16);
        a[3] = lds32(ab + 8 * (WROW * 2) + 16);

        const uint32_t fadr = featb + (h0 + lm_h) * (FEATW * 2) + lm_f * 2;
        #pragma unroll
        for (int fb = 0; fb < 4; fb++) {
            uint32_t r0, r1, r2, r3;
            ldmatrix_x4_t(r0, r1, r2, r3, fadr + fb * 32);
            uint32_t b0[2] = {r0, r1};
            uint32_t b1[2] = {r2, r3};
            mma16816h(acc[fb * 2 + 0], a, b0);
            mma16816h(acc[fb * 2 + 1], a, b1);
        }
    }

    // ---- epilogue: stage frags to smem, then coalesced k-major STG ----
    __syncwarp();   // all ldmatrix reads of featsm done
    #pragma unroll
    for (int nt = 0; nt < 8; nt++) {
        __half2 v0 = __floats2half2_rn(acc[nt][0], acc[nt][1]);
        sts32(featb + (g * 36 + nt * 4 + t) * 4, *(uint32_t*)&v0);
        if (g < 7) {
            __half2 v1 = __floats2half2_rn(acc[nt][2], acc[nt][3]);
            sts32(featb + ((g + 8) * 36 + nt * 4 + t) * 4, *(uint32_t*)&v1);
        }
    }
    __syncwarp();

    // WF[k][p][64]: word row = (k*TOTALP + gp)*32
    uint32_t* wbase = (uint32_t*)g_WF;
    #pragma unroll
    for (int i = 0; i < 15; i++)
        wbase[((size_t)i * TOTALP + gp) * 32 + lane] = lds32(featb + (i * 36 + lane) * 4);
}

// =================================================================
// Kernel 2: out = WF @ KVT^T — WF chunk reads now fully sequential
// =================================================================
__global__ void __launch_bounds__(THREADS_G, 2)
gemm_kernel(float* __restrict__ out)
{
    extern __shared__ char smem[];
    const uint32_t smb = smem_u32(smem);

    const int tid  = threadIdx.x;
    const int wid  = tid >> 5;
    const int lane = tid & 31;
    const int g    = lane >> 2;
    const int t    = lane & 3;
    const int m0   = blockIdx.x * PTS_CTA;
    const int pbase = wid * 32;

    float acc[4][4][4];
    #pragma unroll
    for (int i = 0; i < 4; i++)
        #pragma unroll
        for (int j = 0; j < 4; j++)
            #pragma unroll
            for (int q = 0; q < 4; q++) acc[i][j][q] = 0.0f;

    auto stage_load = [&](int ch, int buf) {
        const uint32_t sb = smb + buf * ST_SIZE;
        // WF chunk: contiguous 256 rows x 128B starting at (ch*TOTALP + m0)*64
        const __half* wsrc = g_WF + ((size_t)ch * TOTALP + m0) * KCH;
        #pragma unroll
        for (int u = tid; u < PTS_CTA * 8; u += THREADS_G) {
            const int r = u >> 3, s = u & 7;
            cpasync16(sb + ST_WF + r * ROWB + s * 16, wsrc + r * KCH + s * 8);
        }
        const size_t koff = (size_t)ch * KCH;
        #pragma unroll
        for (int u = tid; u < CC * 8; u += THREADS_G) {
            const int r = u >> 3, s = u & 7;
            cpasync16(sb + ST_KV + r * ROWB + s * 16,
                      g_KVT + (size_t)r * KF + koff + s * 8);
        }
        cpasync_commit();
    };

    stage_load(0, 0);

    for (int ch = 0; ch < NCH; ch++) {
        if (ch + 1 < NCH) {
            stage_load(ch + 1, (ch + 1) & 1);
            asm volatile("cp.async.wait_group 1;" ::: "memory");
        } else {
            asm volatile("cp.async.wait_group 0;" ::: "memory");
        }
        __syncthreads();

        const uint32_t sb = smb + (ch & 1) * ST_SIZE;

        #pragma unroll
        for (int ks = 0; ks < KCH / 16; ks++) {
            const int kbB = ks * 32;

            uint32_t bh[4][2];
            #pragma unroll
            for (int pt = 0; pt < 4; pt++) {
                const uint32_t rowoff = (pbase + pt * 8 + g) * ROWB + kbB + t * 4;
                bh[pt][0] = lds32(sb + ST_WF + rowoff);
                bh[pt][1] = lds32(sb + ST_WF + rowoff + 16);
            }

            #pragma unroll
            for (int cm = 0; cm < 4; cm++) {
                const uint32_t rowoff = (cm * 16 + g) * ROWB + kbB + t * 4;
                uint32_t ah[4];
                ah[0] = lds32(sb + ST_KV + rowoff);
                ah[1] = lds32(sb + ST_KV + rowoff + 8 * ROWB);
                ah[2] = lds32(sb + ST_KV + rowoff + 16);
                ah[3] = lds32(sb + ST_KV + rowoff + 8 * ROWB + 16);

                #pragma unroll
                for (int pt = 0; pt < 4; pt++)
                    mma16816h(acc[cm][pt], ah, bh[pt]);
            }
        }
        __syncthreads();
    }

    #pragma unroll
    for (int cm = 0; cm < 4; cm++) {
        #pragma unroll
        for (int pt = 0; pt < 4; pt++) {
            const int c0 = cm * 16 + g;
            const int c1 = c0 + 8;
            const size_t p0 = (size_t)m0 + pbase + pt * 8 + t * 2;
            out[p0 * CC + c0]       = acc[cm][pt][0];
            out[(p0 + 1) * CC + c0] = acc[cm][pt][1];
            out[p0 * CC + c1]       = acc[cm][pt][2];
            out[(p0 + 1) * CC + c1] = acc[cm][pt][3];
        }
    }
}

// =================================================================
extern "C" void kernel_launch(void* const* d_in, const int* in_sizes, int n_in,
                              void* d_out, int out_size)
{
    const float* points        = (const float*)d_in[0];
    const float* features      = (const float*)d_in[1];
    const float* output_points = (const float*)d_in[2];
    const float* k_points      = (const float*)d_in[3];
    const float* k_values      = (const float*)d_in[4];
    const int*   neighbor_idx  = (const int*)d_in[5];
    float* out = (float*)d_out;

    static bool attr_done = false;
    if (!attr_done) {
        cudaFuncSetAttribute(gemm_kernel, cudaFuncAttributeMaxDynamicSharedMemorySize, SMEM_G);
        cudaFuncSetAttribute(phaseA_kernel, cudaFuncAttributeMaxDynamicSharedMemorySize, SMEM_A);
        attr_done = true;
    }

    const int feat_elems4 = BB * NN * FF / 4;
    prep_kernel<<<feat_elems4 / 256, 256>>>(features, k_values);
    phaseA_kernel<<<TOTALP / WARPS_A, THREADS_A, SMEM_A>>>(
        points, output_points, k_points, neighbor_idx);
    gemm_kernel<<<TOTALP / PTS_CTA, THREADS_G, SMEM_G>>>(out);
}

// round 14
// speedup vs baseline: 1.0316x; 1.0316x over previous
#include <cuda_runtime.h>
#include <cuda_fp16.h>
#include <cstdint>

#define BB 4
#define NN 16384
#define MM 16384
#define HH 32
#define KK 15
#define FF 64
#define CC 64
#define KF 960
#define TOTALP (BB * MM)      // 65536

// ---------------- Phase-A (HMMA) config ----------------
#define THREADS_A 512         // 16 warps, 1 point per warp
#define WARPS_A 16
#define FEATW 72              // halfs per feat row (144B)
#define WROW  40              // halfs per wT row (80B)
#define WARP_HALFS (HH * FEATW + 16 * WROW)   // 2944
#define SMEM_A (WARPS_A * WARP_HALFS * 2)     // 94208 B

// ---------------- GEMM config (validated R12) ----------------
#define PTS_CTA 256
#define THREADS_G 256
#define KCH 64
#define NCH (KF / KCH)        // 15
#define ROWB 144

#define ST_WF   0
#define ST_KV   (PTS_CTA * ROWB)            // 36864
#define ST_SIZE (ST_KV + CC * ROWB)         // 46080
#define SMEM_G  (2 * ST_SIZE)               // 92160

// ------------- device scratch -------------
__device__ __half g_WF[(size_t)TOTALP * KF];       // 120 MB fp16, point-major
__device__ __half g_feat16[(size_t)BB * NN * FF];  // 8.4 MB fp16 features
__device__ __half g_KVT[CC * KF];                  // [c][kf] fp16

// ------------- helpers -------------
__device__ __forceinline__ uint32_t smem_u32(const void* p) {
    uint32_t a;
    asm("{ .reg .u64 t; cvta.to.shared.u64 t, %1; cvt.u32.u64 %0, t; }" : "=r"(a) : "l"(p));
    return a;
}
__device__ __forceinline__ void cpasync16(uint32_t dst, const void* src) {
    asm volatile("cp.async.cg.shared.global [%0], [%1], 16;" :: "r"(dst), "l"(src));
}
__device__ __forceinline__ void cpasync_commit() { asm volatile("cp.async.commit_group;"); }
__device__ __forceinline__ uint32_t lds32(uint32_t a) {
    uint32_t v; asm volatile("ld.shared.b32 %0, [%1];" : "=r"(v) : "r"(a)); return v;
}
__device__ __forceinline__ void sts32(uint32_t a, uint32_t v) {
    asm volatile("st.shared.b32 [%0], %1;" :: "r"(a), "r"(v));
}
__device__ __forceinline__ float sqrt_approx(float x) {
    float r; asm("sqrt.approx.f32 %0, %1;" : "=f"(r) : "f"(x)); return r;
}
__device__ __forceinline__ void mma16816h(float* c, const uint32_t* a, const uint32_t* b) {
    asm volatile(
        "mma.sync.aligned.m16n8k16.row.col.f32.f16.f16.f32 "
        "{%0,%1,%2,%3}, {%4,%5,%6,%7}, {%8,%9}, {%0,%1,%2,%3};"
        : "+f"(c[0]), "+f"(c[1]), "+f"(c[2]), "+f"(c[3])
        : "r"(a[0]), "r"(a[1]), "r"(a[2]), "r"(a[3]), "r"(b[0]), "r"(b[1]));
}
__device__ __forceinline__ void ldmatrix_x4_t(uint32_t& r0, uint32_t& r1,
                                              uint32_t& r2, uint32_t& r3, uint32_t a) {
    asm volatile("ldmatrix.sync.aligned.m8n8.x4.trans.shared.b16 {%0,%1,%2,%3}, [%4];"
                 : "=r"(r0), "=r"(r1), "=r"(r2), "=r"(r3) : "r"(a));
}

// =================================================================
// Kernel 0: features fp32 -> fp16; first 240 blocks also prep KVT
// =================================================================
__global__ void prep_kernel(const float* __restrict__ features,
                            const float* __restrict__ k_values) {
    const int i = blockIdx.x * blockDim.x + threadIdx.x;
    if (blockIdx.x < 240) {
        const int j = blockIdx.x * 256 + threadIdx.x;   // 61440 = KF*CC
        const int kf = j >> 6, c = j & 63;
        g_KVT[c * KF + kf] = __float2half_rn(k_values[j]);
    }
    const float4 v = ((const float4*)features)[i];
    ((__half2*)g_feat16)[2 * i]     = __floats2half2_rn(v.x, v.y);
    ((__half2*)g_feat16)[2 * i + 1] = __floats2half2_rn(v.z, v.w);
}

// =================================================================
// Kernel 1: Phase A (HMMA) -> WF fp16, staged coalesced epilogue
// =================================================================
__global__ void __launch_bounds__(THREADS_A, 2)
phaseA_kernel(const float* __restrict__ points,
              const float* __restrict__ output_points,
              const float* __restrict__ k_points,
              const int*   __restrict__ neighbor_indices)
{
    extern __shared__ __half smA[];
    __shared__ float kps[KK * 3 + 3];

    const int tid  = threadIdx.x;
    const int warp = tid >> 5;
    const int lane = tid & 31;
    const int g    = lane >> 2;
    const int t    = lane & 3;

    if (tid < KK * 3) kps[tid] = k_points[tid];
    __syncthreads();

    __half* featsm = smA + warp * WARP_HALFS;   // [32][FEATW]
    __half* wsmT   = featsm + HH * FEATW;       // [16][WROW]
    const uint32_t featb = smem_u32(featsm);
    const uint32_t wb    = smem_u32(wsmT);

    const int gp = blockIdx.x * WARPS_A + warp;
    const int b  = gp >> 14;

    // ---- load neighbor idx, immediately issue gather cp.asyncs ----
    const int nidx = neighbor_indices[gp * HH + lane];
    const __half* f16base = g_feat16 + (size_t)b * NN * FF;
    const int s = lane & 7;
    #pragma unroll
    for (int it = 0; it < 8; it++) {
        const int row = it * 4 + (lane >> 3);
        const int ni  = __shfl_sync(0xffffffffu, nidx, row);
        cpasync16(featb + row * (FEATW * 2) + s * 16,
                  f16base + (size_t)ni * FF + s * 8);
    }
    cpasync_commit();

    // ---- w compute (overlaps gather latency): lane = h ----
    wsmT[15 * WROW + lane] = __ushort_as_half(0);
    const float ox = output_points[gp * 3 + 0];
    const float oy = output_points[gp * 3 + 1];
    const float oz = output_points[gp * 3 + 2];
    const float* pp = points + ((size_t)b * NN + nidx) * 3;
    const float rx = pp[0] - ox;
    const float ry = pp[1] - oy;
    const float rz = pp[2] - oz;

    #pragma unroll
    for (int k = 0; k < KK; k++) {
        const float dx = rx - kps[k * 3 + 0];
        const float dy = ry - kps[k * 3 + 1];
        const float dz = rz - kps[k * 3 + 2];
        const float d  = sqrt_approx(fmaf(dx, dx, fmaf(dy, dy, dz * dz)));
        wsmT[k * WROW + lane] = __float2half_rn(fmaxf(1.0f - d, 0.0f));
    }

    asm volatile("cp.async.wait_group 0;" ::: "memory");
    __syncwarp();

    // ---- MMA: D[k16][f64] ----
    float acc[8][4];
    #pragma unroll
    for (int nt = 0; nt < 8; nt++)
        #pragma unroll
        for (int q = 0; q < 4; q++) acc[nt][q] = 0.0f;

    const int lm_h = ((lane >> 3) & 1) * 8 + (lane & 7);
    const int lm_f = ((lane >> 4) & 1) * 8;

    #pragma unroll
    for (int kstep = 0; kstep < 2; kstep++) {
        const int h0 = kstep * 16;
        uint32_t a[4];
        const uint32_t ab = wb + g * (WROW * 2) + kstep * 32 + t * 4;
        a[0] = lds32(ab);
        a[1] = lds32(ab + 8 * (WROW * 2));
        a[2] = lds32(ab + 16);
        a[3] = lds32(ab + 8 * (WROW * 2) + 16);

        const uint32_t fadr = featb + (h0 + lm_h) * (FEATW * 2) + lm_f * 2;
        #pragma unroll
        for (int fb = 0; fb < 4; fb++) {
            uint32_t r0, r1, r2, r3;
            ldmatrix_x4_t(r0, r1, r2, r3, fadr + fb * 32);
            uint32_t b0[2] = {r0, r1};
            uint32_t b1[2] = {r2, r3};
            mma16816h(acc[fb * 2 + 0], a, b0);
            mma16816h(acc[fb * 2 + 1], a, b1);
        }
    }

    // ---- epilogue: stage frags to smem (featsm dead), coalesced STG ----
    __syncwarp();   // all ldmatrix reads of featsm done
    #pragma unroll
    for (int nt = 0; nt < 8; nt++) {
        __half2 v0 = __floats2half2_rn(acc[nt][0], acc[nt][1]);
        sts32(featb + (g * 36 + nt * 4 + t) * 4, *(uint32_t*)&v0);
        if (g < 7) {
            __half2 v1 = __floats2half2_rn(acc[nt][2], acc[nt][3]);
            sts32(featb + ((g + 8) * 36 + nt * 4 + t) * 4, *(uint32_t*)&v1);
        }
    }
    __syncwarp();

    uint32_t* wdst = (uint32_t*)(g_WF + (size_t)gp * KF);
    #pragma unroll
    for (int i = 0; i < 15; i++)
        wdst[i * 32 + lane] = lds32(featb + (i * 36 + lane) * 4);
}

// =================================================================
// Kernel 2: out = WF @ KVT^T (byte-identical to R12)
// =================================================================
__global__ void __launch_bounds__(THREADS_G, 2)
gemm_kernel(float* __restrict__ out)
{
    extern __shared__ char smem[];
    const uint32_t smb = smem_u32(smem);

    const int tid  = threadIdx.x;
    const int wid  = tid >> 5;
    const int lane = tid & 31;
    const int g    = lane >> 2;
    const int t    = lane & 3;
    const int m0   = blockIdx.x * PTS_CTA;
    const int pbase = wid * 32;

    float acc[4][4][4];
    #pragma unroll
    for (int i = 0; i < 4; i++)
        #pragma unroll
        for (int j = 0; j < 4; j++)
            #pragma unroll
            for (int q = 0; q < 4; q++) acc[i][j][q] = 0.0f;

    auto stage_load = [&](int ch, int buf) {
        const size_t koff = (size_t)ch * KCH;
        const uint32_t sb = smb + buf * ST_SIZE;
        #pragma unroll
        for (int u = tid; u < PTS_CTA * 8; u += THREADS_G) {
            const int r = u >> 3, s = u & 7;
            cpasync16(sb + ST_WF + r * ROWB + s * 16,
                      g_WF + (size_t)(m0 + r) * KF + koff + s * 8);
        }
        #pragma unroll
        for (int u = tid; u < CC * 8; u += THREADS_G) {
            const int r = u >> 3, s = u & 7;
            cpasync16(sb + ST_KV + r * ROWB + s * 16,
                      g_KVT + (size_t)r * KF + koff + s * 8);
        }
        cpasync_commit();
    };

    stage_load(0, 0);

    for (int ch = 0; ch < NCH; ch++) {
        if (ch + 1 < NCH) {
            stage_load(ch + 1, (ch + 1) & 1);
            asm volatile("cp.async.wait_group 1;" ::: "memory");
        } else {
            asm volatile("cp.async.wait_group 0;" ::: "memory");
        }
        __syncthreads();

        const uint32_t sb = smb + (ch & 1) * ST_SIZE;

        #pragma unroll
        for (int ks = 0; ks < KCH / 16; ks++) {
            const int kbB = ks * 32;

            uint32_t bh[4][2];
            #pragma unroll
            for (int pt = 0; pt < 4; pt++) {
                const uint32_t rowoff = (pbase + pt * 8 + g) * ROWB + kbB + t * 4;
                bh[pt][0] = lds32(sb + ST_WF + rowoff);
                bh[pt][1] = lds32(sb + ST_WF + rowoff + 16);
            }

            #pragma unroll
            for (int cm = 0; cm < 4; cm++) {
                const uint32_t rowoff = (cm * 16 + g) * ROWB + kbB + t * 4;
                uint32_t ah[4];
                ah[0] = lds32(sb + ST_KV + rowoff);
                ah[1] = lds32(sb + ST_KV + rowoff + 8 * ROWB);
                ah[2] = lds32(sb + ST_KV + rowoff + 16);
                ah[3] = lds32(sb + ST_KV + rowoff + 8 * ROWB + 16);

                #pragma unroll
                for (int pt = 0; pt < 4; pt++)
                    mma16816h(acc[cm][pt], ah, bh[pt]);
            }
        }
        __syncthreads();
    }

    #pragma unroll
    for (int cm = 0; cm < 4; cm++) {
        #pragma unroll
        for (int pt = 0; pt < 4; pt++) {
            const int c0 = cm * 16 + g;
            const int c1 = c0 + 8;
            const size_t p0 = (size_t)m0 + pbase + pt * 8 + t * 2;
            out[p0 * CC + c0]       = acc[cm][pt][0];
            out[(p0 + 1) * CC + c0] = acc[cm][pt][1];
            out[p0 * CC + c1]       = acc[cm][pt][2];
            out[(p0 + 1) * CC + c1] = acc[cm][pt][3];
        }
    }
}

// =================================================================
extern "C" void kernel_launch(void* const* d_in, const int* in_sizes, int n_in,
                              void* d_out, int out_size)
{
    const float* points        = (const float*)d_in[0];
    const float* features      = (const float*)d_in[1];
    const float* output_points = (const float*)d_in[2];
    const float* k_points      = (const float*)d_in[3];
    const float* k_values      = (const float*)d_in[4];
    const int*   neighbor_idx  = (const int*)d_in[5];
    float* out = (float*)d_out;

    static bool attr_done = false;
    if (!attr_done) {
        cudaFuncSetAttribute(gemm_kernel, cudaFuncAttributeMaxDynamicSharedMemorySize, SMEM_G);
        cudaFuncSetAttribute(phaseA_kernel, cudaFuncAttributeMaxDynamicSharedMemorySize, SMEM_A);
        attr_done = true;
    }

    const int feat_elems4 = BB * NN * FF / 4;
    prep_kernel<<<feat_elems4 / 256, 256>>>(features, k_values);
    phaseA_kernel<<<TOTALP / WARPS_A, THREADS_A, SMEM_A>>>(
        points, output_points, k_points, neighbor_idx);
    gemm_kernel<<<TOTALP / PTS_CTA, THREADS_G, SMEM_G>>>(out);
}

// round 15
// speedup vs baseline: 1.1140x; 1.0799x over previous
#include <cuda_runtime.h>
#include <cuda_fp16.h>
#include <cstdint>

#define BB 4
#define NN 16384
#define MM 16384
#define HH 32
#define KK 15
#define FF 64
#define CC 64
#define KF 960
#define TOTALP (BB * MM)      // 65536

// ---------------- Phase-A (HMMA) config ----------------
#define THREADS_A 256         // 8 warps, 1 point per warp
#define WARPS_A 8
#define FEATW 72              // halfs per feat row (144B)
#define WROW  40              // halfs per wT row (80B)
#define WARP_HALFS (HH * FEATW + 16 * WROW)   // 2944
#define SMEM_A (WARPS_A * WARP_HALFS * 2)     // 47104 B

// ---------------- GEMM config (validated R12) ----------------
#define PTS_CTA 256
#define THREADS_G 256
#define KCH 64
#define NCH (KF / KCH)        // 15
#define ROWB 144

#define ST_WF   0
#define ST_KV   (PTS_CTA * ROWB)            // 36864
#define ST_SIZE (ST_KV + CC * ROWB)         // 46080
#define SMEM_G  (2 * ST_SIZE)               // 92160

// ------------- device scratch -------------
__device__ __half g_WF[(size_t)TOTALP * KF];       // 120 MB fp16, point-major
__device__ __half g_feat16[(size_t)BB * NN * FF];  // 8.4 MB fp16 features
__device__ __half g_KVT[CC * KF];                  // [c][kf] fp16
__device__ float4 g_pts4[(size_t)BB * NN];         // 1 MB packed points

// ------------- helpers -------------
__device__ __forceinline__ uint32_t smem_u32(const void* p) {
    uint32_t a;
    asm("{ .reg .u64 t; cvta.to.shared.u64 t, %1; cvt.u32.u64 %0, t; }" : "=r"(a) : "l"(p));
    return a;
}
__device__ __forceinline__ void cpasync16(uint32_t dst, const void* src) {
    asm volatile("cp.async.cg.shared.global [%0], [%1], 16;" :: "r"(dst), "l"(src));
}
__device__ __forceinline__ void cpasync_commit() { asm volatile("cp.async.commit_group;"); }
__device__ __forceinline__ uint32_t lds32(uint32_t a) {
    uint32_t v; asm volatile("ld.shared.b32 %0, [%1];" : "=r"(v) : "r"(a)); return v;
}
__device__ __forceinline__ void sts32(uint32_t a, uint32_t v) {
    asm volatile("st.shared.b32 [%0], %1;" :: "r"(a), "r"(v));
}
__device__ __forceinline__ float sqrt_approx(float x) {
    float r; asm("sqrt.approx.f32 %0, %1;" : "=f"(r) : "f"(x)); return r;
}
__device__ __forceinline__ void mma16816h(float* c, const uint32_t* a, const uint32_t* b) {
    asm volatile(
        "mma.sync.aligned.m16n8k16.row.col.f32.f16.f16.f32 "
        "{%0,%1,%2,%3}, {%4,%5,%6,%7}, {%8,%9}, {%0,%1,%2,%3};"
        : "+f"(c[0]), "+f"(c[1]), "+f"(c[2]), "+f"(c[3])
        : "r"(a[0]), "r"(a[1]), "r"(a[2]), "r"(a[3]), "r"(b[0]), "r"(b[1]));
}
__device__ __forceinline__ void ldmatrix_x4_t(uint32_t& r0, uint32_t& r1,
                                              uint32_t& r2, uint32_t& r3, uint32_t a) {
    asm volatile("ldmatrix.sync.aligned.m8n8.x4.trans.shared.b16 {%0,%1,%2,%3}, [%4];"
                 : "=r"(r0), "=r"(r1), "=r"(r2), "=r"(r3) : "r"(a));
}

// =================================================================
// Kernel 0: feat fp32->fp16; blocks<240 prep KVT; blocks<256 pack points4
// =================================================================
__global__ void prep_kernel(const float* __restrict__ features,
                            const float* __restrict__ k_values,
                            const float* __restrict__ points) {
    const int i = blockIdx.x * blockDim.x + threadIdx.x;
    if (blockIdx.x < 240) {
        const int j = blockIdx.x * 256 + threadIdx.x;   // 61440 = KF*CC
        const int kf = j >> 6, c = j & 63;
        g_KVT[c * KF + kf] = __float2half_rn(k_values[j]);
    }
    if (blockIdx.x < 256) {
        const int p = blockIdx.x * 256 + threadIdx.x;   // 65536 = BB*NN
        const float* pp = points + (size_t)p * 3;
        g_pts4[p] = make_float4(pp[0], pp[1], pp[2], 0.0f);
    }
    const float4 v = ((const float4*)features)[i];
    ((__half2*)g_feat16)[2 * i]     = __floats2half2_rn(v.x, v.y);
    ((__half2*)g_feat16)[2 * i + 1] = __floats2half2_rn(v.z, v.w);
}

// =================================================================
// Kernel 1: Phase A (HMMA) -> WF fp16, staged coalesced epilogue
// =================================================================
__global__ void __launch_bounds__(THREADS_A, 3)
phaseA_kernel(const float* __restrict__ output_points,
              const float* __restrict__ k_points,
              const int*   __restrict__ neighbor_indices)
{
    extern __shared__ __half smA[];
    __shared__ float kps[KK * 3 + 3];

    const int tid  = threadIdx.x;
    const int warp = tid >> 5;
    const int lane = tid & 31;
    const int g    = lane >> 2;
    const int t    = lane & 3;

    if (tid < KK * 3) kps[tid] = k_points[tid];
    __syncthreads();

    __half* featsm = smA + warp * WARP_HALFS;   // [32][FEATW]
    __half* wsmT   = featsm + HH * FEATW;       // [16][WROW]
    const uint32_t featb = smem_u32(featsm);
    const uint32_t wb    = smem_u32(wsmT);

    const int gp = blockIdx.x * WARPS_A + warp;
    const int b  = gp >> 14;

    // ---- load neighbor idx, immediately issue gather cp.asyncs ----
    const int nidx = neighbor_indices[gp * HH + lane];
    const __half* f16base = g_feat16 + (size_t)b * NN * FF;
    const int s = lane & 7;
    #pragma unroll
    for (int it = 0; it < 8; it++) {
        const int row = it * 4 + (lane >> 3);
        const int ni  = __shfl_sync(0xffffffffu, nidx, row);
        cpasync16(featb + row * (FEATW * 2) + s * 16,
                  f16base + (size_t)ni * FF + s * 8);
    }
    cpasync_commit();

    // ---- w compute (overlaps gather latency): lane = h ----
    wsmT[15 * WROW + lane] = __ushort_as_half(0);
    const float ox = output_points[gp * 3 + 0];
    const float oy = output_points[gp * 3 + 1];
    const float oz = output_points[gp * 3 + 2];
    const float4 p4 = g_pts4[(size_t)b * NN + nidx];   // one LDG.128
    const float rx = p4.x - ox;
    const float ry = p4.y - oy;
    const float rz = p4.z - oz;

    #pragma unroll
    for (int k = 0; k < KK; k++) {
        const float dx = rx - kps[k * 3 + 0];
        const float dy = ry - kps[k * 3 + 1];
        const float dz = rz - kps[k * 3 + 2];
        const float d  = sqrt_approx(fmaf(dx, dx, fmaf(dy, dy, dz * dz)));
        wsmT[k * WROW + lane] = __float2half_rn(fmaxf(1.0f - d, 0.0f));
    }

    asm volatile("cp.async.wait_group 0;" ::: "memory");
    __syncwarp();

    // ---- MMA: D[k16][f64] ----
    float acc[8][4];
    #pragma unroll
    for (int nt = 0; nt < 8; nt++)
        #pragma unroll
        for (int q = 0; q < 4; q++) acc[nt][q] = 0.0f;

    const int lm_h = ((lane >> 3) & 1) * 8 + (lane & 7);
    const int lm_f = ((lane >> 4) & 1) * 8;

    #pragma unroll
    for (int kstep = 0; kstep < 2; kstep++) {
        const int h0 = kstep * 16;
        uint32_t a[4];
        const uint32_t ab = wb + g * (WROW * 2) + kstep * 32 + t * 4;
        a[0] = lds32(ab);
        a[1] = lds32(ab + 8 * (WROW * 2));
        a[2] = lds32(ab + 16);
        a[3] = lds32(ab + 8 * (WROW * 2) + 16);

        const uint32_t fadr = featb + (h0 + lm_h) * (FEATW * 2) + lm_f * 2;
        #pragma unroll
        for (int fb = 0; fb < 4; fb++) {
            uint32_t r0, r1, r2, r3;
            ldmatrix_x4_t(r0, r1, r2, r3, fadr + fb * 32);
            uint32_t b0[2] = {r0, r1};
            uint32_t b1[2] = {r2, r3};
            mma16816h(acc[fb * 2 + 0], a, b0);
            mma16816h(acc[fb * 2 + 1], a, b1);
        }
    }

    // ---- epilogue: stage frags to smem (featsm dead), coalesced STG ----
    __syncwarp();   // all ldmatrix reads of featsm done
    #pragma unroll
    for (int nt = 0; nt < 8; nt++) {
        __half2 v0 = __floats2half2_rn(acc[nt][0], acc[nt][1]);
        sts32(featb + (g * 36 + nt * 4 + t) * 4, *(uint32_t*)&v0);
        if (g < 7) {
            __half2 v1 = __floats2half2_rn(acc[nt][2], acc[nt][3]);
            sts32(featb + ((g + 8) * 36 + nt * 4 + t) * 4, *(uint32_t*)&v1);
        }
    }
    __syncwarp();

    uint32_t* wdst = (uint32_t*)(g_WF + (size_t)gp * KF);
    #pragma unroll
    for (int i = 0; i < 15; i++)
        wdst[i * 32 + lane] = lds32(featb + (i * 36 + lane) * 4);
}

// =================================================================
// Kernel 2: out = WF @ KVT^T (byte-identical to R12)
// =================================================================
__global__ void __launch_bounds__(THREADS_G, 2)
gemm_kernel(float* __restrict__ out)
{
    extern __shared__ char smem[];
    const uint32_t smb = smem_u32(smem);

    const int tid  = threadIdx.x;
    const int wid  = tid >> 5;
    const int lane = tid & 31;
    const int g    = lane >> 2;
    const int t    = lane & 3;
    const int m0   = blockIdx.x * PTS_CTA;
    const int pbase = wid * 32;

    float acc[4][4][4];
    #pragma unroll
    for (int i = 0; i < 4; i++)
        #pragma unroll
        for (int j = 0; j < 4; j++)
            #pragma unroll
            for (int q = 0; q < 4; q++) acc[i][j][q] = 0.0f;

    auto stage_load = [&](int ch, int buf) {
        const size_t koff = (size_t)ch * KCH;
        const uint32_t sb = smb + buf * ST_SIZE;
        #pragma unroll
        for (int u = tid; u < PTS_CTA * 8; u += THREADS_G) {
            const int r = u >> 3, s = u & 7;
            cpasync16(sb + ST_WF + r * ROWB + s * 16,
                      g_WF + (size_t)(m0 + r) * KF + koff + s * 8);
        }
        #pragma unroll
        for (int u = tid; u < CC * 8; u += THREADS_G) {
            const int r = u >> 3, s = u & 7;
            cpasync16(sb + ST_KV + r * ROWB + s * 16,
                      g_KVT + (size_t)r * KF + koff + s * 8);
        }
        cpasync_commit();
    };

    stage_load(0, 0);

    for (int ch = 0; ch < NCH; ch++) {
        if (ch + 1 < NCH) {
            stage_load(ch + 1, (ch + 1) & 1);
            asm volatile("cp.async.wait_group 1;" ::: "memory");
        } else {
            asm volatile("cp.async.wait_group 0;" ::: "memory");
        }
        __syncthreads();

        const uint32_t sb = smb + (ch & 1) * ST_SIZE;

        #pragma unroll
        for (int ks = 0; ks < KCH / 16; ks++) {
            const int kbB = ks * 32;

            uint32_t bh[4][2];
            #pragma unroll
            for (int pt = 0; pt < 4; pt++) {
                const uint32_t rowoff = (pbase + pt * 8 + g) * ROWB + kbB + t * 4;
                bh[pt][0] = lds32(sb + ST_WF + rowoff);
                bh[pt][1] = lds32(sb + ST_WF + rowoff + 16);
            }

            #pragma unroll
            for (int cm = 0; cm < 4; cm++) {
                const uint32_t rowoff = (cm * 16 + g) * ROWB + kbB + t * 4;
                uint32_t ah[4];
                ah[0] = lds32(sb + ST_KV + rowoff);
                ah[1] = lds32(sb + ST_KV + rowoff + 8 * ROWB);
                ah[2] = lds32(sb + ST_KV + rowoff + 16);
                ah[3] = lds32(sb + ST_KV + rowoff + 8 * ROWB + 16);

                #pragma unroll
                for (int pt = 0; pt < 4; pt++)
                    mma16816h(acc[cm][pt], ah, bh[pt]);
            }
        }
        __syncthreads();
    }

    #pragma unroll
    for (int cm = 0; cm < 4; cm++) {
        #pragma unroll
        for (int pt = 0; pt < 4; pt++) {
            const int c0 = cm * 16 + g;
            const int c1 = c0 + 8;
            const size_t p0 = (size_t)m0 + pbase + pt * 8 + t * 2;
            out[p0 * CC + c0]       = acc[cm][pt][0];
            out[(p0 + 1) * CC + c0] = acc[cm][pt][1];
            out[p0 * CC + c1]       = acc[cm][pt][2];
            out[(p0 + 1) * CC + c1] = acc[cm][pt][3];
        }
    }
}

// =================================================================
extern "C" void kernel_launch(void* const* d_in, const int* in_sizes, int n_in,
                              void* d_out, int out_size)
{
    const float* points        = (const float*)d_in[0];
    const float* features      = (const float*)d_in[1];
    const float* output_points = (const float*)d_in[2];
    const float* k_points      = (const float*)d_in[3];
    const float* k_values      = (const float*)d_in[4];
    const int*   neighbor_idx  = (const int*)d_in[5];
    float* out = (float*)d_out;

    static bool attr_done = false;
    if (!attr_done) {
        cudaFuncSetAttribute(gemm_kernel, cudaFuncAttributeMaxDynamicSharedMemorySize, SMEM_G);
        cudaFuncSetAttribute(phaseA_kernel, cudaFuncAttributeMaxDynamicSharedMemorySize, SMEM_A);
        attr_done = true;
    }

    const int feat_elems4 = BB * NN * FF / 4;
    prep_kernel<<<feat_elems4 / 256, 256>>>(features, k_values, points);
    phaseA_kernel<<<TOTALP / WARPS_A, THREADS_A, SMEM_A>>>(
        output_points, k_points, neighbor_idx);
    gemm_kernel<<<TOTALP / PTS_CTA, THREADS_G, SMEM_G>>>(out);
}